// round 6
// baseline (speedup 1.0000x reference)
#include <cuda_runtime.h>
#include <math.h>

// Fixed problem shape: A=128 atoms, FR=16 partials, NS=32768 samples, NF=128 frames.
#define FR  16
#define TPB 256
#define KPT 16                      // samples/thread; frame index advances 1 per k
#define NS  32768
#define NBX (NS / (TPB * KPT))      // 8 x-blocks

// 2*pi / 2^32 : signed Q0.32 turns -> radians in [-pi, pi)
#define TURN2RAD 1.4629180792671596e-9f

typedef unsigned long long u64;

// ---- Blackwell packed-fp32 helpers (ptxas never emits these from C++) ----
__device__ __forceinline__ u64 pk2(float lo, float hi) {
    u64 r; asm("mov.b64 %0, {%1, %2};" : "=l"(r) : "f"(lo), "f"(hi)); return r;
}
__device__ __forceinline__ void upk2(u64 v, float& lo, float& hi) {
    asm("mov.b64 {%0, %1}, %2;" : "=f"(lo), "=f"(hi) : "l"(v));
}
__device__ __forceinline__ u64 mul2(u64 a, u64 b) {
    u64 r; asm("mul.rn.f32x2 %0, %1, %2;" : "=l"(r) : "l"(a), "l"(b)); return r;
}
__device__ __forceinline__ u64 add2(u64 a, u64 b) {
    u64 r; asm("add.rn.f32x2 %0, %1, %2;" : "=l"(r) : "l"(a), "l"(b)); return r;
}
__device__ __forceinline__ u64 fma2(u64 a, u64 b, u64 c) {
    u64 r; asm("fma.rn.f32x2 %0, %1, %2, %3;" : "=l"(r) : "l"(a), "l"(b), "l"(c)); return r;
}

// ---------------------------------------------------------------------------
// Block = (atom, 4096-sample tile). Threads 0..15 derive per-partial constants.
// Mainloop: partials processed in PAIRS, each 64-bit register carrying two
// independent damped-sinusoid Goertzel chains (fma.rn.f32x2). Steady state:
// 3 packed fma-pipe ops per TWO samples. Seeds: 2 MUFU.SIN per partial.
// Geometric-decay lerp factorizes into the chain scale exactly; zero
// per-sample memory traffic.
// ---------------------------------------------------------------------------
__global__ void __launch_bounds__(TPB)
synth_kernel(const float* __restrict__ osc,
             const float* __restrict__ amp,
             const float* __restrict__ decay,
             float* __restrict__ out)
{
    __shared__ float4 s_c1[FR];     // {phi, dp, rc, nc2}
    __shared__ float4 s_c2[FR];     // {Eh0, Eh1, a2d, dm1}

    const int a    = blockIdx.y;
    const int bx   = blockIdx.x;
    const int base = bx * (TPB * KPT);
    const int tid  = threadIdx.x;
    const int J    = bx * KPT;

    if (tid < FR) {
        int i = a * FR + tid;
        // freq = fl32( fl32(sigmoid(osc)^2) * fl32(pi) )  (replicate fp32 rounding)
        float o   = osc[i];
        float sgf = (float)(1.0 / (1.0 + exp(-(double)o)));
        float t1  = sgf * sgf;
        float fq  = t1 * 3.14159274101257324219f;              // fl32(pi)
        double f2p = (double)fq * (1.0 / (2.0 * M_PI));
        unsigned phi = (unsigned)llrint(f2p * 4294967296.0);   // Q0.32 turns/sample
        unsigned dp  = phi << 8;                               // 256 samples per k

        float am = amp[i];
        float a2 = am * am * 0.0625f;

        float dv  = decay[i];
        float sgd = (float)(1.0 / (1.0 + exp(-(double)dv)));
        float d   = 0.7f + sgd * 0.299999f;

        float del = (float)(int)dp * TURN2RAD;
        float rc  = 2.0f * d * __cosf(del);
        float nc2 = -(d * d);

        float l2d = (float)log2((double)d);
        float Eh0 = a2 * exp2f((float)J * l2d);                // a2 * d^J
        float Eh1 = Eh0 * d;

        s_c1[tid] = make_float4(__uint_as_float(phi), __uint_as_float(dp), rc, nc2);
        s_c2[tid] = make_float4(Eh0, Eh1, a2 * d, d - 1.0f);
    }
    __syncthreads();

    const int  h  = tid >> 7;
    const float w = fmaf((float)tid, 0.00390625f,
                         h ? -0.498046875f : 0.501953125f);    // lerp weight, const over k
    const unsigned tk1 = (unsigned)(base + tid + 1);
    const bool fix_first = (bx == 0)       && (h == 0);        // pos clamp at k=0
    const bool fix_last  = (bx == NBX - 1) && (h == 1);        // i1 clamp at k=KPT-1

    u64 acc[KPT];
#pragma unroll
    for (int k = 0; k < KPT; k++) acc[k] = 0ull;

#pragma unroll 2
    for (int q = 0; q < FR / 2; q++) {
        const float4 c1a = s_c1[2 * q],     c2a = s_c2[2 * q];
        const float4 c1b = s_c1[2 * q + 1], c2b = s_c2[2 * q + 1];

        // --- scalar per-lane seed math ---
        const float wfa = fmaf(w, c2a.w, 1.0f);                // (1-w) + w*d
        const float wfb = fmaf(w, c2b.w, 1.0f);
        const float Eha = h ? c2a.y : c2a.x;                   // a2 * d^(J+h)
        const float Ehb = h ? c2b.y : c2b.x;
        const float Ewa = Eha * wfa;
        const float Ewb = Ehb * wfb;
        // hoisted: only consumed under the warp-uniform fix_last branch
        const float rwa = __frcp_rn(wfa);
        const float rwb = __frcp_rn(wfb);

        unsigned p0a = tk1 * __float_as_uint(c1a.x);
        unsigned p0b = tk1 * __float_as_uint(c1b.x);
        unsigned p1a = p0a + __float_as_uint(c1a.y);
        unsigned p1b = p0b + __float_as_uint(c1b.y);
        float s0a = __sinf((float)(int)p0a * TURN2RAD);
        float s0b = __sinf((float)(int)p0b * TURN2RAD);
        float s1a = __sinf((float)(int)p1a * TURN2RAD);
        float s1b = __sinf((float)(int)p1b * TURN2RAD);

        float y0a = s0a * Ewa,                   y0b = s0b * Ewb;                   // y[0]
        float y1a = s1a * fmaf(Ewa, c2a.w, Ewa), y1b = s1b * fmaf(Ewb, c2b.w, Ewb); // y[1]

        // acc[0]: clamp fixup uses a2*d exactly when pos clamped to 0
        float e0a = fix_first ? (s0a * c2a.z) : y0a;
        float e0b = fix_first ? (s0b * c2b.z) : y0b;

        // --- pack into f32x2 chains ---
        const u64 RC  = pk2(c1a.z, c1b.z);
        const u64 NC2 = pk2(c1a.w, c1b.w);
        u64 Ykm2 = pk2(y0a, y0b);
        u64 Ykm1 = pk2(y1a, y1b);

        acc[0] = add2(acc[0], pk2(e0a, e0b));
        acc[1] = add2(acc[1], Ykm1);

#pragma unroll
        for (int k = 2; k < KPT; k++) {
            u64 Y = fma2(RC, Ykm1, mul2(NC2, Ykm2));           // 2 damped chains per op
            if (k == KPT - 1 && fix_last) {
                float ya, yb; upk2(Y, ya, yb);                  // strip lerp factor:
                u64 Yc = pk2(ya * rwa, yb * rwb);               // D = d^128 exact
                acc[k] = add2(acc[k], Yc);
            } else {
                acc[k] = add2(acc[k], Y);
            }
            Ykm2 = Ykm1;  Ykm1 = Y;
        }
    }

    float* o = out + (size_t)a * NS + base + tid;
#pragma unroll
    for (int k = 0; k < KPT; k++) {
        float lo, hi; upk2(acc[k], lo, hi);
        o[k * TPB] = lo + hi;
    }
}

// ---------------------------------------------------------------------------
extern "C" void kernel_launch(void* const* d_in, const int* in_sizes, int n_in,
                              void* d_out, int out_size)
{
    const float* osc   = (const float*)d_in[0];
    const float* amp   = (const float*)d_in[1];
    const float* decay = (const float*)d_in[2];

    int A = in_sizes[0] / FR;

    dim3 grid(NBX, A);                      // (8, 128)
    synth_kernel<<<grid, TPB>>>(osc, amp, decay, (float*)d_out);
}

// round 9
// speedup vs baseline: 1.0759x; 1.0759x over previous
#include <cuda_runtime.h>
#include <cuda_bf16.h>
#include <math.h>

// Fixed shape: A=128 atoms, FR=16 partials, NS=32768 samples, NF=128 frames.
// t = 128*T + tau,  T in [0,256),  tau in [0,128).
// out[a, 128T+tau] = sum_k A[tau,k] * C[T,k],  K = 192:
//   k in [0,64):    Ah * Ch      k in [64,128): Al * Ch      k in [128,192): Ah * Cl
// Basis per partial f: {sin(w*tau), cos(w*tau), ts*sin, ts*cos}, ts = tau/128.
// Coeff per (T,f): {P*al*cosT, P*al*sinT, P*be*cosT, P*be*sinT}, angle w*(128T+1);
// al,be from the exact per-half-frame linear decay (lerp of geometric table).
#define FR   16
#define NS   32768
#define TPB  256
#define PAD  200                    // bf16 per smem row (192 + 8 pad)

#define TURN2RAD 1.4629180792671596e-9f   // 2*pi / 2^32

// smem layout (bytes)
#define SM_PAR 0                    // float4[16]
#define SM_DEC 256                  // float[16*128]
#define SM_A   8448                 // bf16[128*200]  (51200 B)
#define SM_C   59648                // bf16[256*200]  (102400 B)
#define SM_D   162048               // float[64*132]  (33792 B) - own region
#define SM_TOTAL 195840

typedef unsigned u32;

static __device__ __forceinline__ void mma16816(float* d, const u32* a, u32 b0, u32 b1) {
    asm volatile(
        "mma.sync.aligned.m16n8k16.row.col.f32.bf16.bf16.f32 "
        "{%0,%1,%2,%3}, {%4,%5,%6,%7}, {%8,%9}, {%0,%1,%2,%3};"
        : "+f"(d[0]), "+f"(d[1]), "+f"(d[2]), "+f"(d[3])
        : "r"(a[0]), "r"(a[1]), "r"(a[2]), "r"(a[3]), "r"(b0), "r"(b1));
}

static __device__ __forceinline__ void split_bf16(float v, __nv_bfloat16& h, __nv_bfloat16& l) {
    h = __float2bfloat16(v);
    l = __float2bfloat16(v - __bfloat162float(h));
}

// ---------------------------------------------------------------------------
__global__ void __launch_bounds__(TPB, 1)
synth_mma_kernel(const float* __restrict__ osc,
                 const float* __restrict__ amp,
                 const float* __restrict__ decay,
                 float* __restrict__ out)
{
    extern __shared__ char smem[];
    float4*        par = (float4*)(smem + SM_PAR);    // {phi bits, P, d, log2 d}
    float*         dec = (float*) (smem + SM_DEC);    // dec[f*128+j] = d^(j+1)
    __nv_bfloat16* As  = (__nv_bfloat16*)(smem + SM_A);
    __nv_bfloat16* Cs  = (__nv_bfloat16*)(smem + SM_C);
    float*         Ds  = (float*) (smem + SM_D);

    const int tid = threadIdx.x;
    const int a   = blockIdx.x;

    // --- per-partial params (replicate reference fp32 rounding chain) ---
    if (tid < FR) {
        int i = a * FR + tid;
        float o   = osc[i];
        float sgf = (float)(1.0 / (1.0 + exp(-(double)o)));
        float fq  = (sgf * sgf) * 3.14159274101257324219f;     // fl32(pi)
        double f2p = (double)fq * (1.0 / (2.0 * M_PI));
        u32 phi = (u32)llrint(f2p * 4294967296.0);             // Q0.32 turns/sample

        float am = amp[i];
        float P  = am * am * 0.0625f;

        float dv  = decay[i];
        float sgd = (float)(1.0 / (1.0 + exp(-(double)dv)));
        float d   = 0.7f + sgd * 0.299999f;
        float l2d = (float)log2((double)d);
        par[tid] = make_float4(__uint_as_float(phi), P, d, l2d);
    }
    __syncthreads();

    // --- decay table + A (basis) tile ---
    for (int idx = tid; idx < FR * 128; idx += TPB) {
        int f = idx >> 7, j = idx & 127;
        dec[idx] = exp2f((float)(j + 1) * par[f].w);
    }
    for (int idx = tid; idx < FR * 128; idx += TPB) {
        int tau = idx & 127, f = idx >> 7;
        u32 phi = __float_as_uint(par[f].x);
        u32 p   = (u32)tau * phi;
        float x = (float)(int)p * TURN2RAD;
        float s = __sinf(x), c = __cosf(x);
        float ts = (float)tau * 0.0078125f;
        float v[4] = { s, c, s * ts, c * ts };
        __nv_bfloat16 h[4], l[4];
#pragma unroll
        for (int q = 0; q < 4; q++) split_bf16(v[q], h[q], l[q]);
        __nv_bfloat16* row = As + tau * PAD + 4 * f;
        *(__nv_bfloat162*)(row)       = __nv_bfloat162(h[0], h[1]);   // Ah
        *(__nv_bfloat162*)(row + 2)   = __nv_bfloat162(h[2], h[3]);
        *(__nv_bfloat162*)(row + 64)  = __nv_bfloat162(l[0], l[1]);   // Al
        *(__nv_bfloat162*)(row + 66)  = __nv_bfloat162(l[2], l[3]);
        *(__nv_bfloat162*)(row + 128) = __nv_bfloat162(h[0], h[1]);   // Ah (dup)
        *(__nv_bfloat162*)(row + 130) = __nv_bfloat162(h[2], h[3]);
    }
    __syncthreads();

    // --- C (coefficient) tile: needs dec ---
    for (int idx = tid; idx < FR * 256; idx += TPB) {
        int T = idx & 255, f = idx >> 8;
        float4 pr = par[f];
        u32 phi = __float_as_uint(pr.x);
        float P = pr.y, d = pr.z;

        float al, be;
        if (T == 0)        { al = dec[f * 128];       be = 0.0f; }
        else if (T == 255) { al = dec[f * 128 + 127]; be = 0.0f; }
        else {
            int   i0 = (T - 1) >> 1;
            float w0 = (T & 1) ? 0.001953125f : 0.501953125f;
            float dj = dec[f * 128 + i0];
            float dm1 = d - 1.0f;
            al = dj * fmaf(w0, dm1, 1.0f);
            be = dj * dm1 * 0.5f;              // coefficient of ts = tau/128
        }
        u32 p   = (u32)(128 * T + 1) * phi;
        float x = (float)(int)p * TURN2RAD;
        float SA = __sinf(x), CA = __cosf(x);
        float Pal = P * al, Pbe = P * be;
        float e[4] = { Pal * CA, Pal * SA, Pbe * CA, Pbe * SA };
        __nv_bfloat16 h[4], l[4];
#pragma unroll
        for (int q = 0; q < 4; q++) split_bf16(e[q], h[q], l[q]);
        __nv_bfloat16* row = Cs + T * PAD + 4 * f;
        *(__nv_bfloat162*)(row)       = __nv_bfloat162(h[0], h[1]);   // Ch
        *(__nv_bfloat162*)(row + 2)   = __nv_bfloat162(h[2], h[3]);
        *(__nv_bfloat162*)(row + 64)  = __nv_bfloat162(h[0], h[1]);   // Ch (pairs Al)
        *(__nv_bfloat162*)(row + 66)  = __nv_bfloat162(h[2], h[3]);
        *(__nv_bfloat162*)(row + 128) = __nv_bfloat162(l[0], l[1]);   // Cl (pairs Ah)
        *(__nv_bfloat162*)(row + 130) = __nv_bfloat162(l[2], l[3]);
    }
    __syncthreads();

    // --- MMA, two passes over the N halves: T in [nh*128, nh*128+128) ---
    const int w    = tid >> 5, lane = tid & 31;
    const int g    = lane >> 2, qi = lane & 3;
    const int mh   = w >> 2,    nw = w & 3;

#pragma unroll 1
    for (int nh = 0; nh < 2; nh++) {
        float acc[4][4][4];
#pragma unroll
        for (int mt = 0; mt < 4; mt++)
#pragma unroll
            for (int nt = 0; nt < 4; nt++)
#pragma unroll
                for (int q = 0; q < 4; q++) acc[mt][nt][q] = 0.0f;

#pragma unroll 1
        for (int kt = 0; kt < 12; kt++) {
            const int kb = kt * 16;
            u32 afr[4][4];
#pragma unroll
            for (int mt = 0; mt < 4; mt++) {
                const __nv_bfloat16* r0 = As + (mh * 64 + mt * 16 + g) * PAD + kb + 2 * qi;
                afr[mt][0] = *(const u32*)(r0);
                afr[mt][1] = *(const u32*)(r0 + 8 * PAD);
                afr[mt][2] = *(const u32*)(r0 + 8);
                afr[mt][3] = *(const u32*)(r0 + 8 * PAD + 8);
            }
#pragma unroll
            for (int nt = 0; nt < 4; nt++) {
                const __nv_bfloat16* rc =
                    Cs + (nh * 128 + nw * 32 + nt * 8 + g) * PAD + kb + 2 * qi;
                u32 b0 = *(const u32*)(rc);
                u32 b1 = *(const u32*)(rc + 8);
#pragma unroll
                for (int mt = 0; mt < 4; mt++)
                    mma16816(acc[mt][nt], afr[mt], b0, b1);
            }
        }
        __syncthreads();

        // --- epilogue for this half: two 64-T chunks staged through Ds ---
#pragma unroll 1
        for (int c = 0; c < 2; c++) {
            if ((nw >> 1) == c) {
#pragma unroll
                for (int nt = 0; nt < 4; nt++)
#pragma unroll
                    for (int mt = 0; mt < 4; mt++) {
                        int Tl  = nw * 32 + nt * 8 + 2 * qi - c * 64;   // 0..62
                        int tau = mh * 64 + mt * 16 + g;
                        float* bs = Ds + Tl * 132;
                        bs[tau]           = acc[mt][nt][0];
                        bs[132 + tau]     = acc[mt][nt][1];
                        bs[tau + 8]       = acc[mt][nt][2];
                        bs[132 + tau + 8] = acc[mt][nt][3];
                    }
            }
            __syncthreads();
            float* ob = out + (size_t)a * NS + (size_t)(nh * 128 + c * 64) * 128;
#pragma unroll
            for (int r = 0; r < 8; r++) {
                int T    = r * 8 + (tid >> 5);
                int tau0 = 4 * (tid & 31);
                float4 v = *(float4*)(Ds + T * 132 + tau0);
                *(float4*)(ob + (size_t)T * 128 + tau0) = v;
            }
            __syncthreads();
        }
    }
}

// ---------------------------------------------------------------------------
extern "C" void kernel_launch(void* const* d_in, const int* in_sizes, int n_in,
                              void* d_out, int out_size)
{
    const float* osc   = (const float*)d_in[0];
    const float* amp   = (const float*)d_in[1];
    const float* decay = (const float*)d_in[2];

    int A = in_sizes[0] / FR;

    cudaFuncSetAttribute(synth_mma_kernel,
                         cudaFuncAttributeMaxDynamicSharedMemorySize, SM_TOTAL);
    synth_mma_kernel<<<A, TPB, SM_TOTAL>>>(osc, amp, decay, (float*)d_out);
}

// round 10
// speedup vs baseline: 1.1109x; 1.0325x over previous
#include <cuda_runtime.h>
#include <cuda_bf16.h>
#include <math.h>

// Fixed shape: A=128 atoms, FR=16 partials, NS=32768 samples, NF=128 frames.
// t = 128*T + tau, T in [0,256), tau in [0,128).
// out[a, 128T+tau] = sum over 3 K-blocks of 64: Ah*Ch + Al*Ch + Ah*Cl
// (hi/lo bf16 split of basis and coefficients; K-blocks realized by address
//  mapping in the fragment loads, not duplicated smem.)
// CTA = (atom, T-half): grid (128, 2). 2 CTAs/SM co-resident.
#define FR   16
#define NS   32768
#define TPB  256
#define PAD  136                    // bf16 per smem row (128 + 8); 68 words = 4 mod 32

#define TURN2RAD 1.4629180792671596e-9f   // 2*pi / 2^32

// smem layout (bytes)
#define SM_PAR 0                    // float4[16]
#define SM_DEC 256                  // float[16*128]
#define SM_A   8448                 // bf16[128*136] = 34816  {Ah | Al}
#define SM_C   43264                // bf16[128*136] = 34816  {Ch | Cl}
#define SM_D   78080                // float[32*132] = 16896
#define SM_TOTAL 94976

typedef unsigned u32;

static __device__ __forceinline__ void mma16816(float* d, const u32* a, u32 b0, u32 b1) {
    asm volatile(
        "mma.sync.aligned.m16n8k16.row.col.f32.bf16.bf16.f32 "
        "{%0,%1,%2,%3}, {%4,%5,%6,%7}, {%8,%9}, {%0,%1,%2,%3};"
        : "+f"(d[0]), "+f"(d[1]), "+f"(d[2]), "+f"(d[3])
        : "r"(a[0]), "r"(a[1]), "r"(a[2]), "r"(a[3]), "r"(b0), "r"(b1));
}

static __device__ __forceinline__ void split_bf16(float v, __nv_bfloat16& h, __nv_bfloat16& l) {
    h = __float2bfloat16(v);
    l = __float2bfloat16(v - __bfloat162float(h));
}

// ---------------------------------------------------------------------------
__global__ void __launch_bounds__(TPB)
synth_mma_kernel(const float* __restrict__ osc,
                 const float* __restrict__ amp,
                 const float* __restrict__ decay,
                 float* __restrict__ out)
{
    extern __shared__ char smem[];
    float4*        par = (float4*)(smem + SM_PAR);    // {phi bits, P, d, log2 d}
    float*         dec = (float*) (smem + SM_DEC);    // dec[f*128+j] = d^(j+1)
    __nv_bfloat16* As  = (__nv_bfloat16*)(smem + SM_A);
    __nv_bfloat16* Cs  = (__nv_bfloat16*)(smem + SM_C);
    float*         Ds  = (float*) (smem + SM_D);

    const int tid = threadIdx.x;
    const int a   = blockIdx.x;
    const int nh  = blockIdx.y;                       // T-half: T in [nh*128, nh*128+128)

    // --- per-partial params (replicate reference fp32 rounding chain) ---
    if (tid < FR) {
        int i = a * FR + tid;
        float o   = osc[i];
        float sgf = (float)(1.0 / (1.0 + exp(-(double)o)));
        float fq  = (sgf * sgf) * 3.14159274101257324219f;     // fl32(pi)
        double f2p = (double)fq * (1.0 / (2.0 * M_PI));
        u32 phi = (u32)llrint(f2p * 4294967296.0);             // Q0.32 turns/sample

        float am = amp[i];
        float P  = am * am * 0.0625f;

        float dv  = decay[i];
        float sgd = (float)(1.0 / (1.0 + exp(-(double)dv)));
        float d   = 0.7f + sgd * 0.299999f;
        float l2d = (float)log2((double)d);
        par[tid] = make_float4(__uint_as_float(phi), P, d, l2d);
    }
    __syncthreads();

    // --- decay table + A (basis) tile {Ah | Al} ---
    for (int idx = tid; idx < FR * 128; idx += TPB) {
        int f = idx >> 7, j = idx & 127;
        dec[idx] = exp2f((float)(j + 1) * par[f].w);
    }
    for (int idx = tid; idx < FR * 128; idx += TPB) {
        int tau = idx & 127, f = idx >> 7;
        u32 phi = __float_as_uint(par[f].x);
        u32 p   = (u32)tau * phi;
        float x = (float)(int)p * TURN2RAD;
        float s = __sinf(x), c = __cosf(x);
        float ts = (float)tau * 0.0078125f;
        float v[4] = { s, c, s * ts, c * ts };
        __nv_bfloat16 h[4], l[4];
#pragma unroll
        for (int q = 0; q < 4; q++) split_bf16(v[q], h[q], l[q]);
        __nv_bfloat16* row = As + tau * PAD + 4 * f;
        *(__nv_bfloat162*)(row)      = __nv_bfloat162(h[0], h[1]);   // Ah
        *(__nv_bfloat162*)(row + 2)  = __nv_bfloat162(h[2], h[3]);
        *(__nv_bfloat162*)(row + 64) = __nv_bfloat162(l[0], l[1]);   // Al
        *(__nv_bfloat162*)(row + 66) = __nv_bfloat162(l[2], l[3]);
    }
    __syncthreads();

    // --- C (coefficient) tile {Ch | Cl}: 128 local T rows (needs dec) ---
    for (int idx = tid; idx < FR * 128; idx += TPB) {
        int Tl = idx & 127, f = idx >> 7;
        int T  = nh * 128 + Tl;
        float4 pr = par[f];
        u32 phi = __float_as_uint(pr.x);
        float P = pr.y, d = pr.z;

        float al, be;
        if (T == 0)        { al = dec[f * 128];       be = 0.0f; }
        else if (T == 255) { al = dec[f * 128 + 127]; be = 0.0f; }
        else {
            int   i0 = (T - 1) >> 1;
            float w0 = (T & 1) ? 0.001953125f : 0.501953125f;
            float dj = dec[f * 128 + i0];
            float dm1 = d - 1.0f;
            al = dj * fmaf(w0, dm1, 1.0f);
            be = dj * dm1 * 0.5f;              // coefficient of ts = tau/128
        }
        u32 p   = (u32)(128 * T + 1) * phi;
        float x = (float)(int)p * TURN2RAD;
        float SA = __sinf(x), CA = __cosf(x);
        float Pal = P * al, Pbe = P * be;
        float e[4] = { Pal * CA, Pal * SA, Pbe * CA, Pbe * SA };
        __nv_bfloat16 h[4], l[4];
#pragma unroll
        for (int q = 0; q < 4; q++) split_bf16(e[q], h[q], l[q]);
        __nv_bfloat16* row = Cs + Tl * PAD + 4 * f;
        *(__nv_bfloat162*)(row)      = __nv_bfloat162(h[0], h[1]);   // Ch
        *(__nv_bfloat162*)(row + 2)  = __nv_bfloat162(h[2], h[3]);
        *(__nv_bfloat162*)(row + 64) = __nv_bfloat162(l[0], l[1]);   // Cl
        *(__nv_bfloat162*)(row + 66) = __nv_bfloat162(l[2], l[3]);
    }
    __syncthreads();

    // --- MMA: D[128 tau x 128 Tl]. warp = (mh m-half, nw 32-T stripe). ---
    const int w    = tid >> 5, lane = tid & 31;
    const int g    = lane >> 2, qi = lane & 3;
    const int mh   = w >> 2,    nw = w & 3;

    float acc[4][4][4];
#pragma unroll
    for (int mt = 0; mt < 4; mt++)
#pragma unroll
        for (int nt = 0; nt < 4; nt++)
#pragma unroll
            for (int q = 0; q < 4; q++) acc[mt][nt][q] = 0.0f;

    // 12 K-steps of 16; K-block pairing by address mapping:
    //   kt 0-3 : Ah[kt]   * Ch[kt]      kt 4-7 : Al[kt-4] * Ch[kt-4]
    //   kt 8-11: Ah[kt-8] * Cl[kt-8]
#pragma unroll 1
    for (int kt = 0; kt < 12; kt++) {
        const int kq = kt & 3;
        const int ka = (kt >= 4 && kt < 8) ? (64 + kq * 16) : (kq * 16);
        const int kc = (kt >= 8)           ? (64 + kq * 16) : (kq * 16);
        u32 afr[4][4];
#pragma unroll
        for (int mt = 0; mt < 4; mt++) {
            const __nv_bfloat16* r0 = As + (mh * 64 + mt * 16 + g) * PAD + ka + 2 * qi;
            afr[mt][0] = *(const u32*)(r0);
            afr[mt][1] = *(const u32*)(r0 + 8 * PAD);
            afr[mt][2] = *(const u32*)(r0 + 8);
            afr[mt][3] = *(const u32*)(r0 + 8 * PAD + 8);
        }
#pragma unroll
        for (int nt = 0; nt < 4; nt++) {
            const __nv_bfloat16* rc = Cs + (nw * 32 + nt * 8 + g) * PAD + kc + 2 * qi;
            u32 b0 = *(const u32*)(rc);
            u32 b1 = *(const u32*)(rc + 8);
#pragma unroll
            for (int mt = 0; mt < 4; mt++)
                mma16816(acc[mt][nt], afr[mt], b0, b1);
        }
    }
    __syncthreads();

    // --- epilogue: four 32-T chunks staged through Ds, coalesced STG.128 ---
#pragma unroll 1
    for (int c = 0; c < 4; c++) {
        if (nw == c) {
#pragma unroll
            for (int nt = 0; nt < 4; nt++)
#pragma unroll
                for (int mt = 0; mt < 4; mt++) {
                    int Tl  = nt * 8 + 2 * qi;                 // 0..30 within chunk
                    int tau = mh * 64 + mt * 16 + g;
                    float* bs = Ds + Tl * 132;
                    bs[tau]           = acc[mt][nt][0];
                    bs[132 + tau]     = acc[mt][nt][1];
                    bs[tau + 8]       = acc[mt][nt][2];
                    bs[132 + tau + 8] = acc[mt][nt][3];
                }
        }
        __syncthreads();
        float* ob = out + (size_t)a * NS + (size_t)(nh * 128 + c * 32) * 128;
#pragma unroll
        for (int r = 0; r < 4; r++) {
            int T    = r * 8 + w;                              // 0..31
            int tau0 = 4 * lane;
            float4 v = *(float4*)(Ds + T * 132 + tau0);
            *(float4*)(ob + (size_t)T * 128 + tau0) = v;
        }
        __syncthreads();
    }
}

// ---------------------------------------------------------------------------
extern "C" void kernel_launch(void* const* d_in, const int* in_sizes, int n_in,
                              void* d_out, int out_size)
{
    const float* osc   = (const float*)d_in[0];
    const float* amp   = (const float*)d_in[1];
    const float* decay = (const float*)d_in[2];

    int A = in_sizes[0] / FR;

    cudaFuncSetAttribute(synth_mma_kernel,
                         cudaFuncAttributeMaxDynamicSharedMemorySize, SM_TOTAL);
    dim3 grid(A, 2);
    synth_mma_kernel<<<grid, TPB, SM_TOTAL>>>(osc, amp, decay, (float*)d_out);
}

// round 11
// speedup vs baseline: 1.1304x; 1.0175x over previous
#include <cuda_runtime.h>
#include <cuda_bf16.h>
#include <math.h>

// Fixed shape: A=128 atoms, FR=16 partials, NS=32768 samples, NF=128 frames.
// t = 128*T + tau, T in [0,256), tau in [0,128).
// out[a, 128T+tau] = Ah*Ch + Al*Ch + Ah*Cl  (hi/lo bf16 split, K-blocks of 64
// realized by address mapping). CTA = (atom, T-quarter): grid (128, 4).
#define FR   16
#define NS   32768
#define TPB  256
#define PAD  136                    // bf16 per smem row (128+8); 68 words = 4 mod 32

#define TURN2RAD 1.4629180792671596e-9f   // 2*pi / 2^32

// smem layout (bytes)
#define SM_PAR 0                    // float4[16]
#define SM_A   256                  // bf16[128*136] = 34816  {Ah | Al}
#define SM_C   35072                // bf16[ 64*136] = 17408  {Ch | Cl}
#define SM_TOTAL 52480

typedef unsigned u32;

static __device__ __forceinline__ void mma16816(float* d, const u32* a, u32 b0, u32 b1) {
    asm volatile(
        "mma.sync.aligned.m16n8k16.row.col.f32.bf16.bf16.f32 "
        "{%0,%1,%2,%3}, {%4,%5,%6,%7}, {%8,%9}, {%0,%1,%2,%3};"
        : "+f"(d[0]), "+f"(d[1]), "+f"(d[2]), "+f"(d[3])
        : "r"(a[0]), "r"(a[1]), "r"(a[2]), "r"(a[3]), "r"(b0), "r"(b1));
}

static __device__ __forceinline__ void split_bf16(float v, __nv_bfloat16& h, __nv_bfloat16& l) {
    h = __float2bfloat16(v);
    l = __float2bfloat16(v - __bfloat162float(h));
}

// ---------------------------------------------------------------------------
__global__ void __launch_bounds__(TPB, 3)
synth_mma_kernel(const float* __restrict__ osc,
                 const float* __restrict__ amp,
                 const float* __restrict__ decay,
                 float* __restrict__ out)
{
    extern __shared__ char smem[];
    float4*        par = (float4*)(smem + SM_PAR);    // {phi bits, P, d, log2 d}
    __nv_bfloat16* As  = (__nv_bfloat16*)(smem + SM_A);
    __nv_bfloat16* Cs  = (__nv_bfloat16*)(smem + SM_C);

    const int tid = threadIdx.x;
    const int a   = blockIdx.x;
    const int nh  = blockIdx.y;                       // T-quarter: T = nh*64 + Tl

    // --- per-partial params (replicate reference fp32 rounding chain) ---
    if (tid < FR) {
        int i = a * FR + tid;
        float o   = osc[i];
        float sgf = (float)(1.0 / (1.0 + exp(-(double)o)));
        float fq  = (sgf * sgf) * 3.14159274101257324219f;     // fl32(pi)
        double f2p = (double)fq * (1.0 / (2.0 * M_PI));
        u32 phi = (u32)llrint(f2p * 4294967296.0);             // Q0.32 turns/sample

        float am = amp[i];
        float P  = am * am * 0.0625f;

        float dv  = decay[i];
        float sgd = (float)(1.0 / (1.0 + exp(-(double)dv)));
        float d   = 0.7f + sgd * 0.299999f;
        float l2d = (float)log2((double)d);
        par[tid] = make_float4(__uint_as_float(phi), P, d, l2d);
    }
    __syncthreads();

    // --- A (basis) tile {Ah | Al}: 128 tau rows ---
    for (int idx = tid; idx < FR * 128; idx += TPB) {
        int tau = idx & 127, f = idx >> 7;
        u32 phi = __float_as_uint(par[f].x);
        u32 p   = (u32)tau * phi;
        float x = (float)(int)p * TURN2RAD;
        float s = __sinf(x), c = __cosf(x);
        float ts = (float)tau * 0.0078125f;
        float v[4] = { s, c, s * ts, c * ts };
        __nv_bfloat16 h[4], l[4];
#pragma unroll
        for (int q = 0; q < 4; q++) split_bf16(v[q], h[q], l[q]);
        __nv_bfloat16* row = As + tau * PAD + 4 * f;
        *(__nv_bfloat162*)(row)      = __nv_bfloat162(h[0], h[1]);   // Ah
        *(__nv_bfloat162*)(row + 2)  = __nv_bfloat162(h[2], h[3]);
        *(__nv_bfloat162*)(row + 64) = __nv_bfloat162(l[0], l[1]);   // Al
        *(__nv_bfloat162*)(row + 66) = __nv_bfloat162(l[2], l[3]);
    }

    // --- C (coefficient) tile {Ch | Cl}: 64 local T rows ---
    for (int idx = tid; idx < FR * 64; idx += TPB) {
        int Tl = idx & 63, f = idx >> 6;
        int T  = nh * 64 + Tl;
        float4 pr = par[f];
        u32 phi = __float_as_uint(pr.x);
        float P = pr.y, d = pr.z, l2d = pr.w;

        float al, be;
        if (T == 0)        { al = exp2f(l2d);          be = 0.0f; }
        else if (T == 255) { al = exp2f(128.0f * l2d); be = 0.0f; }
        else {
            int   i0 = (T - 1) >> 1;
            float w0 = (T & 1) ? 0.001953125f : 0.501953125f;
            float dj = exp2f((float)(i0 + 1) * l2d);   // d^(i0+1)
            float dm1 = d - 1.0f;
            al = dj * fmaf(w0, dm1, 1.0f);
            be = dj * dm1 * 0.5f;              // coefficient of ts = tau/128
        }
        u32 p   = (u32)(128 * T + 1) * phi;
        float x = (float)(int)p * TURN2RAD;
        float SA = __sinf(x), CA = __cosf(x);
        float Pal = P * al, Pbe = P * be;
        float e[4] = { Pal * CA, Pal * SA, Pbe * CA, Pbe * SA };
        __nv_bfloat16 h[4], l[4];
#pragma unroll
        for (int q = 0; q < 4; q++) split_bf16(e[q], h[q], l[q]);
        __nv_bfloat16* row = Cs + Tl * PAD + 4 * f;
        *(__nv_bfloat162*)(row)      = __nv_bfloat162(h[0], h[1]);   // Ch
        *(__nv_bfloat162*)(row + 2)  = __nv_bfloat162(h[2], h[3]);
        *(__nv_bfloat162*)(row + 64) = __nv_bfloat162(l[0], l[1]);   // Cl
        *(__nv_bfloat162*)(row + 66) = __nv_bfloat162(l[2], l[3]);
    }
    __syncthreads();

    // --- MMA: D[128 tau x 64 Tl]. warp = (mh tau-half, nw 16-T stripe). ---
    const int w    = tid >> 5, lane = tid & 31;
    const int g    = lane >> 2, qi = lane & 3;
    const int mh   = w >> 2,    nw = w & 3;

    float acc[4][2][4];
#pragma unroll
    for (int mt = 0; mt < 4; mt++)
#pragma unroll
        for (int nt = 0; nt < 2; nt++)
#pragma unroll
            for (int q = 0; q < 4; q++) acc[mt][nt][q] = 0.0f;

    // kq loop with fragment reuse: per kq load Ah once -> Ah*Ch + Ah*Cl,
    // then reload the same regs with Al -> Al*Ch.
#pragma unroll 1
    for (int kq = 0; kq < 4; kq++) {
        const int ka = kq * 16;
        u32 bH[2][2], bL[2][2];
#pragma unroll
        for (int nt = 0; nt < 2; nt++) {
            const __nv_bfloat16* rc = Cs + (nw * 16 + nt * 8 + g) * PAD + ka + 2 * qi;
            bH[nt][0] = *(const u32*)(rc);
            bH[nt][1] = *(const u32*)(rc + 8);
            bL[nt][0] = *(const u32*)(rc + 64);
            bL[nt][1] = *(const u32*)(rc + 72);
        }
        u32 afr[4][4];
#pragma unroll
        for (int mt = 0; mt < 4; mt++) {                 // Ah fragments
            const __nv_bfloat16* r0 = As + (mh * 64 + mt * 16 + g) * PAD + ka + 2 * qi;
            afr[mt][0] = *(const u32*)(r0);
            afr[mt][1] = *(const u32*)(r0 + 8 * PAD);
            afr[mt][2] = *(const u32*)(r0 + 8);
            afr[mt][3] = *(const u32*)(r0 + 8 * PAD + 8);
        }
#pragma unroll
        for (int nt = 0; nt < 2; nt++)
#pragma unroll
            for (int mt = 0; mt < 4; mt++)
                mma16816(acc[mt][nt], afr[mt], bH[nt][0], bH[nt][1]);   // Ah*Ch
#pragma unroll
        for (int nt = 0; nt < 2; nt++)
#pragma unroll
            for (int mt = 0; mt < 4; mt++)
                mma16816(acc[mt][nt], afr[mt], bL[nt][0], bL[nt][1]);   // Ah*Cl
#pragma unroll
        for (int mt = 0; mt < 4; mt++) {                 // Al fragments (reuse regs)
            const __nv_bfloat16* r0 = As + (mh * 64 + mt * 16 + g) * PAD + 64 + ka + 2 * qi;
            afr[mt][0] = *(const u32*)(r0);
            afr[mt][1] = *(const u32*)(r0 + 8 * PAD);
            afr[mt][2] = *(const u32*)(r0 + 8);
            afr[mt][3] = *(const u32*)(r0 + 8 * PAD + 8);
        }
#pragma unroll
        for (int nt = 0; nt < 2; nt++)
#pragma unroll
            for (int mt = 0; mt < 4; mt++)
                mma16816(acc[mt][nt], afr[mt], bH[nt][0], bH[nt][1]);   // Al*Ch
    }

    // --- epilogue: direct STG.32; each quad-row is one exact 32B sector ---
    float* ob = out + (size_t)a * NS + (size_t)(nh * 64 + nw * 16) * 128;
#pragma unroll
    for (int nt = 0; nt < 2; nt++)
#pragma unroll
        for (int mt = 0; mt < 4; mt++) {
            float* b = ob + (size_t)(nt * 8 + 2 * qi) * 128 + mh * 64 + mt * 16 + g;
            b[0]       = acc[mt][nt][0];
            b[128]     = acc[mt][nt][1];
            b[8]       = acc[mt][nt][2];
            b[136]     = acc[mt][nt][3];
        }
}

// ---------------------------------------------------------------------------
extern "C" void kernel_launch(void* const* d_in, const int* in_sizes, int n_in,
                              void* d_out, int out_size)
{
    const float* osc   = (const float*)d_in[0];
    const float* amp   = (const float*)d_in[1];
    const float* decay = (const float*)d_in[2];

    int A = in_sizes[0] / FR;

    cudaFuncSetAttribute(synth_mma_kernel,
                         cudaFuncAttributeMaxDynamicSharedMemorySize, SM_TOTAL);
    dim3 grid(A, 4);
    synth_mma_kernel<<<grid, TPB, SM_TOTAL>>>(osc, amp, decay, (float*)d_out);
}